// round 7
// baseline (speedup 1.0000x reference)
#include <cuda_runtime.h>

// Shapes (fixed by dataset): b=4, n1=16384, n2=4096, Cout=64, Cin(x2)=128.
#define COUT 64
#define PTS  32      // points per block in VN kernels
#define KCH  64      // k-chunk staged in smem
#define GS   16      // grid cells per axis
#define NCELLS (GS*GS*GS)

typedef unsigned long long ull;

// Scratch (allocation-free contract -> __device__ globals)
__device__ float  g_y2[COUT * 3 * 16384];   // y2 in [o][v][N2] layout
__device__ int    g_kidx[65536 * 3];
__device__ float  g_kw[65536 * 3];
__device__ int    g_ccnt[4 * NCELLS];       // per-cell counts
__device__ int    g_cstart[4 * NCELLS];     // per-cell exclusive starts (batch-local)
__device__ int    g_cur[4 * NCELLS];        // scatter cursors
__device__ float4 g_p2s[4 * 4096];          // reordered points: (x,y,z, idx-as-float)

// ---- packed f32x2 helpers (FFMA2 path, PTX-only on sm_103a) ----------------
__device__ __forceinline__ ull fma2(ull a, ull b, ull c) {
    ull d;
    asm("fma.rn.f32x2 %0, %1, %2, %3;" : "=l"(d) : "l"(a), "l"(b), "l"(c));
    return d;
}
__device__ __forceinline__ ull pack2(float x, float y) {
    ull d;
    asm("mov.b64 %0, {%1, %2};" : "=l"(d) : "f"(x), "f"(y));
    return d;
}
__device__ __forceinline__ float2 unpack2(ull v) {
    float2 r;
    asm("mov.b64 {%0, %1}, %2;" : "=f"(r.x), "=f"(r.y) : "l"(v));
    return r;
}

// ---------------------------------------------------------------------------
// VN linear + leaky-ReLU. Block = 256 threads = 8 ogroups x 32 points.
// Each thread owns 8 out-channels (4 packed pairs) x 3 vector comps.
// ---------------------------------------------------------------------------
template <bool GATHER>
__global__ void __launch_bounds__(256, 3) vn_kernel(
    const float* __restrict__ x,    // [Cin][3][N]
    const float* __restrict__ Wf,   // [COUT][Cin]
    const float* __restrict__ Wd,   // [COUT][Cin]
    float* __restrict__ out,        // [COUT][3][N] (used when GATHER)
    int Cin, int N, int N2)
{
    __shared__ __align__(16) float wfs[KCH * COUT];
    __shared__ __align__(16) float wds[KCH * COUT];

    const int tid  = threadIdx.x;
    const int lane = tid & 31;
    const int og   = tid >> 5;             // 0..7
    const int pt   = blockIdx.x * PTS + lane;
    const bool valid = (pt < N);
    const int ptc  = valid ? pt : (N - 1);

    ull pacc[4][3], dacc[4][3];            // pairs of out-channels
#pragma unroll
    for (int j = 0; j < 4; j++)
#pragma unroll
        for (int v = 0; v < 3; v++) { pacc[j][v] = 0ull; dacc[j][v] = 0ull; }

    for (int k0 = 0; k0 < Cin; k0 += KCH) {
        __syncthreads();
        const int kend = min(KCH, Cin - k0);
        for (int i = tid; i < kend * COUT; i += 256) {
            int o  = i / kend;
            int kk = i - o * kend;
            wfs[kk * COUT + o] = Wf[o * Cin + k0 + kk];
            wds[kk * COUT + o] = Wd[o * Cin + k0 + kk];
        }
        __syncthreads();

#pragma unroll 4
        for (int kk = 0; kk < kend; kk++) {
            const int kb = (k0 + kk) * 3;
            const float xv0 = __ldg(&x[(kb + 0) * N + ptc]);
            const float xv1 = __ldg(&x[(kb + 1) * N + ptc]);
            const float xv2 = __ldg(&x[(kb + 2) * N + ptc]);
            ull xp[3];
            xp[0] = pack2(xv0, xv0);
            xp[1] = pack2(xv1, xv1);
            xp[2] = pack2(xv2, xv2);
            const ulonglong2* wf2 = (const ulonglong2*)&wfs[kk * COUT + og * 8];
            const ulonglong2* wd2 = (const ulonglong2*)&wds[kk * COUT + og * 8];
            const ulonglong2 f01 = wf2[0], f23 = wf2[1];
            const ulonglong2 d01 = wd2[0], d23 = wd2[1];
            const ull fw[4] = {f01.x, f01.y, f23.x, f23.y};
            const ull dw[4] = {d01.x, d01.y, d23.x, d23.y};
#pragma unroll
            for (int j = 0; j < 4; j++) {
#pragma unroll
                for (int v = 0; v < 3; v++) {
                    pacc[j][v] = fma2(fw[j], xp[v], pacc[j][v]);
                    dacc[j][v] = fma2(dw[j], xp[v], dacc[j][v]);
                }
            }
        }
    }

    // interpolation gather (K3 only)
    int   j0 = 0, j1 = 0, j2 = 0;
    float w0 = 0.f, w1 = 0.f, w2 = 0.f;
    if (GATHER) {
        j0 = g_kidx[ptc * 3 + 0];
        j1 = g_kidx[ptc * 3 + 1];
        j2 = g_kidx[ptc * 3 + 2];
        w0 = g_kw[ptc * 3 + 0];
        w1 = g_kw[ptc * 3 + 1];
        w2 = g_kw[ptc * 3 + 2];
    }

    if (!valid) return;

    float* dst = GATHER ? out : g_y2;
#pragma unroll
    for (int j = 0; j < 4; j++) {
        const float2 pv[3] = {unpack2(pacc[j][0]), unpack2(pacc[j][1]), unpack2(pacc[j][2])};
        const float2 dv[3] = {unpack2(dacc[j][0]), unpack2(dacc[j][1]), unpack2(dacc[j][2])};
#pragma unroll
        for (int h = 0; h < 2; h++) {
            const int o = og * 8 + 2 * j + h;
            const float p0 = h ? pv[0].y : pv[0].x;
            const float p1 = h ? pv[1].y : pv[1].x;
            const float p2 = h ? pv[2].y : pv[2].x;
            const float d0 = h ? dv[0].y : dv[0].x;
            const float d1 = h ? dv[1].y : dv[1].x;
            const float d2 = h ? dv[2].y : dv[2].x;
            const float dot = p0 * d0 + p1 * d1 + p2 * d2;
            const float dd  = d0 * d0 + d1 * d1 + d2 * d2;
            // out = p - (dot<0 ? 0.8*dot/(dd+eps) : 0) * d
            const float c = (dot >= 0.f) ? 0.f : (0.8f * dot / (dd + 1e-6f));
            float r0 = p0 - c * d0;
            float r1 = p1 - c * d1;
            float r2 = p2 - c * d2;
            if (GATHER) {
                const int b0i = (o * 3 + 0) * N2;
                const int b1i = (o * 3 + 1) * N2;
                const int b2i = (o * 3 + 2) * N2;
                r0 += w0 * __ldg(&g_y2[b0i + j0]) + w1 * __ldg(&g_y2[b0i + j1]) + w2 * __ldg(&g_y2[b0i + j2]);
                r1 += w0 * __ldg(&g_y2[b1i + j0]) + w1 * __ldg(&g_y2[b1i + j1]) + w2 * __ldg(&g_y2[b1i + j2]);
                r2 += w0 * __ldg(&g_y2[b2i + j0]) + w1 * __ldg(&g_y2[b2i + j1]) + w2 * __ldg(&g_y2[b2i + j2]);
            }
            dst[(o * 3 + 0) * N + pt] = r0;
            dst[(o * 3 + 1) * N + pt] = r1;
            dst[(o * 3 + 2) * N + pt] = r2;
        }
    }
}

// ---------------------------------------------------------------------------
// Grid build: zero -> count -> scan -> scatter (reordered float4 w/ index)
// ---------------------------------------------------------------------------
__device__ __forceinline__ int cell_of(float x, float y, float z) {
    int cx = min(GS - 1, max(0, (int)(x * (float)GS)));
    int cy = min(GS - 1, max(0, (int)(y * (float)GS)));
    int cz = min(GS - 1, max(0, (int)(z * (float)GS)));
    return (cz * GS + cy) * GS + cx;
}

__global__ void grid_zero(int b) {
    int i = blockIdx.x * 256 + threadIdx.x;
    if (i < b * NCELLS) { g_ccnt[i] = 0; g_cur[i] = 0; }
}

__global__ void grid_count(const float* __restrict__ p2, int n2) {
    int i = blockIdx.x * 256 + threadIdx.x;
    int bI = blockIdx.y;
    if (i >= n2) return;
    const int g = bI * n2 + i;
    atomicAdd(&g_ccnt[bI * NCELLS + cell_of(p2[g*3], p2[g*3+1], p2[g*3+2])], 1);
}

// one 1024-thread block per batch; each thread scans 4 cells
__global__ void grid_scan() {
    __shared__ int sums[1024];
    const int bI = blockIdx.x, tid = threadIdx.x;
    const int base = bI * NCELLS;
    int c[4], loc[4];
    int t = 0;
#pragma unroll
    for (int j = 0; j < 4; j++) { c[j] = g_ccnt[base + tid * 4 + j]; loc[j] = t; t += c[j]; }
    sums[tid] = t;
    __syncthreads();
    for (int off = 1; off < 1024; off <<= 1) {
        int v = (tid >= off) ? sums[tid - off] : 0;
        __syncthreads();
        sums[tid] += v;
        __syncthreads();
    }
    const int before = (tid > 0) ? sums[tid - 1] : 0;
#pragma unroll
    for (int j = 0; j < 4; j++) g_cstart[base + tid * 4 + j] = before + loc[j];
}

__global__ void grid_scatter(const float* __restrict__ p2, int n2) {
    int i = blockIdx.x * 256 + threadIdx.x;
    int bI = blockIdx.y;
    if (i >= n2) return;
    const int g = bI * n2 + i;
    const float x = p2[g*3], y = p2[g*3+1], z = p2[g*3+2];
    const int cell = bI * NCELLS + cell_of(x, y, z);
    const int pos = g_cstart[cell] + atomicAdd(&g_cur[cell], 1);
    g_p2s[bI * n2 + pos] = make_float4(x, y, z, __int_as_float(i));
}

// ---------------------------------------------------------------------------
// Exact k=3 NN via expanding Chebyshev shells over the grid.
// Exact non-fma d^2; (d2, idx) lexicographic order matches top_k tie-break
// and makes the result independent of (nondeterministic) scatter order.
// ---------------------------------------------------------------------------
__global__ void __launch_bounds__(256) knn_grid_kernel(
    const float* __restrict__ p1, int n1, int n2)
{
    const int bI = blockIdx.y;
    const int fi = blockIdx.x * 256 + threadIdx.x;
    if (fi >= n1) return;
    const int gq = bI * n1 + fi;
    const float qx = p1[gq*3], qy = p1[gq*3+1], qz = p1[gq*3+2];
    const int qcx = min(GS-1, max(0, (int)(qx * (float)GS)));
    const int qcy = min(GS-1, max(0, (int)(qy * (float)GS)));
    const int qcz = min(GS-1, max(0, (int)(qz * (float)GS)));
    const int cbase = bI * NCELLS;
    const float4* __restrict__ pts = g_p2s + bI * n2;
    const float h = 1.0f / (float)GS;

    float b0 = 3.4e38f, b1 = 3.4e38f, b2 = 3.4e38f;
    int   i0 = 0x7fffffff, i1 = 0x7fffffff, i2 = 0x7fffffff;

    for (int R = 0; R <= GS; R++) {
        const int xlo = max(0, qcx - R), xhi = min(GS-1, qcx + R);
        const int ylo = max(0, qcy - R), yhi = min(GS-1, qcy + R);
        const int zlo = max(0, qcz - R), zhi = min(GS-1, qcz + R);

        for (int z = zlo; z <= zhi; z++) {
            const bool ze = (z == qcz - R) || (z == qcz + R);
            for (int y = ylo; y <= yhi; y++) {
                const bool ye = (y == qcy - R) || (y == qcy + R);
                int xs, xe, xstep;
                if (ze || ye) { xs = xlo; xe = xhi; xstep = 1; }
                else {
                    // only the two x-extreme cells belong to this shell
                    xs = qcx - R; xe = qcx + R; xstep = (R == 0) ? 1 : 2 * R;
                    if (xs < 0)    xs += xstep;
                    if (xe > GS-1) xe -= xstep;
                    if (xstep == 0) xstep = 1;
                }
                for (int x = xs; x <= xe; x += xstep) {
                    const int cell = cbase + (z * GS + y) * GS + x;
                    const int st  = __ldg(&g_cstart[cell]);
                    const int cnt = __ldg(&g_ccnt[cell]);
                    for (int t = 0; t < cnt; t++) {
                        const float4 s = __ldg(&pts[st + t]);
                        const float dx = qx - s.x, dy = qy - s.y, dz = qz - s.z;
                        const float d2 = __fadd_rn(__fadd_rn(__fmul_rn(dx,dx), __fmul_rn(dy,dy)), __fmul_rn(dz,dz));
                        const int idx = __float_as_int(s.w);
                        const bool lt2 = (d2 < b2) || (d2 == b2 && idx < i2);
                        if (lt2) {
                            const bool lt1 = (d2 < b1) || (d2 == b1 && idx < i1);
                            const bool lt0 = (d2 < b0) || (d2 == b0 && idx < i0);
                            if (lt0)      { b2=b1;i2=i1; b1=b0;i1=i0; b0=d2;i0=idx; }
                            else if (lt1) { b2=b1;i2=i1; b1=d2;i1=idx; }
                            else          { b2=d2;i2=idx; }
                        }
                    }
                }
            }
        }

        // full-coverage termination
        if (xlo == 0 && xhi == GS-1 && ylo == 0 && yhi == GS-1 && zlo == 0 && zhi == GS-1)
            break;
        // pruning bound: any unvisited point lies outside the searched box
        if (b2 < 3.4e38f) {
            const float dmx = fmaxf(0.f, fmaxf((float)(qcx - R) * h - qx, qx - (float)(qcx + R + 1) * h));
            const float dmy = fmaxf(0.f, fmaxf((float)(qcy - R) * h - qy, qy - (float)(qcy + R + 1) * h));
            const float dmz = fmaxf(0.f, fmaxf((float)(qcz - R) * h - qz, qz - (float)(qcz + R + 1) * h));
            const float dmin2 = (dmx*dmx + dmy*dmy + dmz*dmz) * 0.999999f;
            if (dmin2 > b2) break;
        }
    }

    const float w0 = 1.f / (b0 + 1e-8f);
    const float w1 = 1.f / (b1 + 1e-8f);
    const float w2 = 1.f / (b2 + 1e-8f);
    const float inv = 1.f / (w0 + w1 + w2);

    const int fo = gq * 3;
    g_kidx[fo + 0] = bI * n2 + i0;
    g_kidx[fo + 1] = bI * n2 + i1;
    g_kidx[fo + 2] = bI * n2 + i2;
    g_kw[fo + 0] = w0 * inv;
    g_kw[fo + 1] = w1 * inv;
    g_kw[fo + 2] = w2 * inv;
}

// ---------------------------------------------------------------------------
// Inputs (metadata order): p1, x1, o1, p2, x2, o2, w1_feat, w1_dir, w2_feat, w2_dir
// ---------------------------------------------------------------------------
extern "C" void kernel_launch(void* const* d_in, const int* in_sizes, int n_in,
                              void* d_out, int out_size)
{
    const float* p1  = (const float*)d_in[0];
    const float* x1  = (const float*)d_in[1];
    const float* p2  = (const float*)d_in[3];
    const float* x2  = (const float*)d_in[4];
    const float* w1f = (const float*)d_in[6];
    const float* w1d = (const float*)d_in[7];
    const float* w2f = (const float*)d_in[8];
    const float* w2d = (const float*)d_in[9];
    float* out = (float*)d_out;

    const int b    = in_sizes[2];              // 4
    const int N1   = in_sizes[0] / 3;          // 65536
    const int N2   = in_sizes[3] / 3;          // 16384
    const int Cin1 = in_sizes[1] / (3 * N1);   // 64
    const int Cin2 = in_sizes[4] / (3 * N2);   // 128
    const int n1   = N1 / b;
    const int n2   = N2 / b;

    // K1: y2 = VN(x2)  ->  g_y2
    vn_kernel<false><<<(N2 + PTS - 1) / PTS, 256>>>(x2, w2f, w2d, nullptr, Cin2, N2, 0);

    // Grid build + K2: exact k=3 NN  ->  g_kidx / g_kw
    grid_zero<<<(b * NCELLS + 255) / 256, 256>>>(b);
    dim3 cg((n2 + 255) / 256, b);
    grid_count<<<cg, 256>>>(p2, n2);
    grid_scan<<<b, 1024>>>();
    grid_scatter<<<cg, 256>>>(p2, n2);
    dim3 qg((n1 + 255) / 256, b);
    knn_grid_kernel<<<qg, 256>>>(p1, n1, n2);

    // K3: out = VN(x1) + interp(g_y2)
    vn_kernel<true><<<(N1 + PTS - 1) / PTS, 256>>>(x1, w1f, w1d, out, Cin1, N1, N2);
}

// round 13
// speedup vs baseline: 1.0225x; 1.0225x over previous
#include <cuda_runtime.h>

// Shapes (fixed by dataset): b=4, n1=16384, n2=4096, Cout=64, Cin(x2)=128.
#define COUT 64
#define PTS  32      // points per block in VN kernels
#define KCH  64      // k-chunk staged in smem
#define GS   16      // grid cells per axis
#define NCELLS (GS*GS*GS)

typedef unsigned long long ull;

// Scratch (allocation-free contract -> __device__ globals)
__device__ float  g_y2[COUT * 3 * 16384];   // y2 in [o][v][N2] layout
__device__ int    g_kidx[65536 * 3];
__device__ float  g_kw[65536 * 3];
__device__ int    g_ccnt[4 * NCELLS];       // per-cell counts
__device__ int    g_cstart[4 * NCELLS];     // per-cell exclusive starts (batch-local)
__device__ int    g_cur[4 * NCELLS];        // scatter cursors
__device__ float4 g_p2s[4 * 4096];          // reordered points: (x,y,z, idx-as-float)

// ---- packed f32x2 helpers (FFMA2 path, PTX-only on sm_103a) ----------------
__device__ __forceinline__ ull fma2(ull a, ull b, ull c) {
    ull d;
    asm("fma.rn.f32x2 %0, %1, %2, %3;" : "=l"(d) : "l"(a), "l"(b), "l"(c));
    return d;
}
__device__ __forceinline__ ull pack2(float x, float y) {
    ull d;
    asm("mov.b64 %0, {%1, %2};" : "=l"(d) : "f"(x), "f"(y));
    return d;
}
__device__ __forceinline__ float2 unpack2(ull v) {
    float2 r;
    asm("mov.b64 {%0, %1}, %2;" : "=f"(r.x), "=f"(r.y) : "l"(v));
    return r;
}

// ---------------------------------------------------------------------------
// VN linear + leaky-ReLU. Block = 256 threads = 8 ogroups x 32 points.
// Each thread owns 8 out-channels (4 packed pairs) x 3 vector comps.
// NOTE: occ cap 2 (NOT 3) — 106 regs live; forcing 3 CTAs spills the 48
// accumulator regs into local memory and inflates the kernel ~10-30x.
// ---------------------------------------------------------------------------
template <bool GATHER>
__global__ void __launch_bounds__(256, 2) vn_kernel(
    const float* __restrict__ x,    // [Cin][3][N]
    const float* __restrict__ Wf,   // [COUT][Cin]
    const float* __restrict__ Wd,   // [COUT][Cin]
    float* __restrict__ out,        // [COUT][3][N] (used when GATHER)
    int Cin, int N, int N2)
{
    __shared__ __align__(16) float wfs[KCH * COUT];
    __shared__ __align__(16) float wds[KCH * COUT];

    const int tid  = threadIdx.x;
    const int lane = tid & 31;
    const int og   = tid >> 5;             // 0..7
    const int pt   = blockIdx.x * PTS + lane;
    const bool valid = (pt < N);
    const int ptc  = valid ? pt : (N - 1);

    ull pacc[4][3], dacc[4][3];            // pairs of out-channels
#pragma unroll
    for (int j = 0; j < 4; j++)
#pragma unroll
        for (int v = 0; v < 3; v++) { pacc[j][v] = 0ull; dacc[j][v] = 0ull; }

    for (int k0 = 0; k0 < Cin; k0 += KCH) {
        __syncthreads();
        const int kend = min(KCH, Cin - k0);
        for (int i = tid; i < kend * COUT; i += 256) {
            int o  = i / kend;
            int kk = i - o * kend;
            wfs[kk * COUT + o] = Wf[o * Cin + k0 + kk];
            wds[kk * COUT + o] = Wd[o * Cin + k0 + kk];
        }
        __syncthreads();

#pragma unroll 4
        for (int kk = 0; kk < kend; kk++) {
            const int kb = (k0 + kk) * 3;
            const float xv0 = __ldg(&x[(kb + 0) * N + ptc]);
            const float xv1 = __ldg(&x[(kb + 1) * N + ptc]);
            const float xv2 = __ldg(&x[(kb + 2) * N + ptc]);
            ull xp[3];
            xp[0] = pack2(xv0, xv0);
            xp[1] = pack2(xv1, xv1);
            xp[2] = pack2(xv2, xv2);
            const ulonglong2* wf2 = (const ulonglong2*)&wfs[kk * COUT + og * 8];
            const ulonglong2* wd2 = (const ulonglong2*)&wds[kk * COUT + og * 8];
            const ulonglong2 f01 = wf2[0], f23 = wf2[1];
            const ulonglong2 d01 = wd2[0], d23 = wd2[1];
            const ull fw[4] = {f01.x, f01.y, f23.x, f23.y};
            const ull dw[4] = {d01.x, d01.y, d23.x, d23.y};
#pragma unroll
            for (int j = 0; j < 4; j++) {
#pragma unroll
                for (int v = 0; v < 3; v++) {
                    pacc[j][v] = fma2(fw[j], xp[v], pacc[j][v]);
                    dacc[j][v] = fma2(dw[j], xp[v], dacc[j][v]);
                }
            }
        }
    }

    // interpolation gather (K3 only)
    int   j0 = 0, j1 = 0, j2 = 0;
    float w0 = 0.f, w1 = 0.f, w2 = 0.f;
    if (GATHER) {
        j0 = g_kidx[ptc * 3 + 0];
        j1 = g_kidx[ptc * 3 + 1];
        j2 = g_kidx[ptc * 3 + 2];
        w0 = g_kw[ptc * 3 + 0];
        w1 = g_kw[ptc * 3 + 1];
        w2 = g_kw[ptc * 3 + 2];
    }

    if (!valid) return;

    float* dst = GATHER ? out : g_y2;
#pragma unroll
    for (int j = 0; j < 4; j++) {
        const float2 pv[3] = {unpack2(pacc[j][0]), unpack2(pacc[j][1]), unpack2(pacc[j][2])};
        const float2 dv[3] = {unpack2(dacc[j][0]), unpack2(dacc[j][1]), unpack2(dacc[j][2])};
#pragma unroll
        for (int h = 0; h < 2; h++) {
            const int o = og * 8 + 2 * j + h;
            const float p0 = h ? pv[0].y : pv[0].x;
            const float p1 = h ? pv[1].y : pv[1].x;
            const float p2 = h ? pv[2].y : pv[2].x;
            const float d0 = h ? dv[0].y : dv[0].x;
            const float d1 = h ? dv[1].y : dv[1].x;
            const float d2 = h ? dv[2].y : dv[2].x;
            const float dot = p0 * d0 + p1 * d1 + p2 * d2;
            const float dd  = d0 * d0 + d1 * d1 + d2 * d2;
            // out = p - (dot<0 ? 0.8*dot/(dd+eps) : 0) * d
            const float c = (dot >= 0.f) ? 0.f : (0.8f * dot / (dd + 1e-6f));
            float r0 = p0 - c * d0;
            float r1 = p1 - c * d1;
            float r2 = p2 - c * d2;
            if (GATHER) {
                const int b0i = (o * 3 + 0) * N2;
                const int b1i = (o * 3 + 1) * N2;
                const int b2i = (o * 3 + 2) * N2;
                r0 += w0 * __ldg(&g_y2[b0i + j0]) + w1 * __ldg(&g_y2[b0i + j1]) + w2 * __ldg(&g_y2[b0i + j2]);
                r1 += w0 * __ldg(&g_y2[b1i + j0]) + w1 * __ldg(&g_y2[b1i + j1]) + w2 * __ldg(&g_y2[b1i + j2]);
                r2 += w0 * __ldg(&g_y2[b2i + j0]) + w1 * __ldg(&g_y2[b2i + j1]) + w2 * __ldg(&g_y2[b2i + j2]);
            }
            dst[(o * 3 + 0) * N + pt] = r0;
            dst[(o * 3 + 1) * N + pt] = r1;
            dst[(o * 3 + 2) * N + pt] = r2;
        }
    }
}

// ---------------------------------------------------------------------------
// Grid build: zero -> count -> scan -> scatter (reordered float4 w/ index)
// ---------------------------------------------------------------------------
__device__ __forceinline__ int cell_of(float x, float y, float z) {
    int cx = min(GS - 1, max(0, (int)(x * (float)GS)));
    int cy = min(GS - 1, max(0, (int)(y * (float)GS)));
    int cz = min(GS - 1, max(0, (int)(z * (float)GS)));
    return (cz * GS + cy) * GS + cx;
}

__global__ void grid_zero(int b) {
    int i = blockIdx.x * 256 + threadIdx.x;
    if (i < b * NCELLS) { g_ccnt[i] = 0; g_cur[i] = 0; }
}

__global__ void grid_count(const float* __restrict__ p2, int n2) {
    int i = blockIdx.x * 256 + threadIdx.x;
    int bI = blockIdx.y;
    if (i >= n2) return;
    const int g = bI * n2 + i;
    atomicAdd(&g_ccnt[bI * NCELLS + cell_of(p2[g*3], p2[g*3+1], p2[g*3+2])], 1);
}

// one 1024-thread block per batch; each thread scans 4 cells
__global__ void grid_scan() {
    __shared__ int sums[1024];
    const int bI = blockIdx.x, tid = threadIdx.x;
    const int base = bI * NCELLS;
    int c[4], loc[4];
    int t = 0;
#pragma unroll
    for (int j = 0; j < 4; j++) { c[j] = g_ccnt[base + tid * 4 + j]; loc[j] = t; t += c[j]; }
    sums[tid] = t;
    __syncthreads();
    for (int off = 1; off < 1024; off <<= 1) {
        int v = (tid >= off) ? sums[tid - off] : 0;
        __syncthreads();
        sums[tid] += v;
        __syncthreads();
    }
    const int before = (tid > 0) ? sums[tid - 1] : 0;
#pragma unroll
    for (int j = 0; j < 4; j++) g_cstart[base + tid * 4 + j] = before + loc[j];
}

__global__ void grid_scatter(const float* __restrict__ p2, int n2) {
    int i = blockIdx.x * 256 + threadIdx.x;
    int bI = blockIdx.y;
    if (i >= n2) return;
    const int g = bI * n2 + i;
    const float x = p2[g*3], y = p2[g*3+1], z = p2[g*3+2];
    const int cell = bI * NCELLS + cell_of(x, y, z);
    const int pos = g_cstart[cell] + atomicAdd(&g_cur[cell], 1);
    g_p2s[bI * n2 + pos] = make_float4(x, y, z, __int_as_float(i));
}

// ---------------------------------------------------------------------------
// Exact k=3 NN via expanding Chebyshev shells over the grid.
// Exact non-fma d^2; (d2, idx) lexicographic order matches top_k tie-break
// and makes the result independent of (nondeterministic) scatter order.
// ---------------------------------------------------------------------------
__global__ void __launch_bounds__(256) knn_grid_kernel(
    const float* __restrict__ p1, int n1, int n2)
{
    const int bI = blockIdx.y;
    const int fi = blockIdx.x * 256 + threadIdx.x;
    if (fi >= n1) return;
    const int gq = bI * n1 + fi;
    const float qx = p1[gq*3], qy = p1[gq*3+1], qz = p1[gq*3+2];
    const int qcx = min(GS-1, max(0, (int)(qx * (float)GS)));
    const int qcy = min(GS-1, max(0, (int)(qy * (float)GS)));
    const int qcz = min(GS-1, max(0, (int)(qz * (float)GS)));
    const int cbase = bI * NCELLS;
    const float4* __restrict__ pts = g_p2s + bI * n2;
    const float h = 1.0f / (float)GS;

    float b0 = 3.4e38f, b1 = 3.4e38f, b2 = 3.4e38f;
    int   i0 = 0x7fffffff, i1 = 0x7fffffff, i2 = 0x7fffffff;

    for (int R = 0; R <= GS; R++) {
        const int xlo = max(0, qcx - R), xhi = min(GS-1, qcx + R);
        const int ylo = max(0, qcy - R), yhi = min(GS-1, qcy + R);
        const int zlo = max(0, qcz - R), zhi = min(GS-1, qcz + R);

        for (int z = zlo; z <= zhi; z++) {
            const bool ze = (z == qcz - R) || (z == qcz + R);
            for (int y = ylo; y <= yhi; y++) {
                const bool ye = (y == qcy - R) || (y == qcy + R);
                int xs, xe, xstep;
                if (ze || ye) { xs = xlo; xe = xhi; xstep = 1; }
                else {
                    // only the two x-extreme cells belong to this shell
                    xs = qcx - R; xe = qcx + R; xstep = (R == 0) ? 1 : 2 * R;
                    if (xs < 0)    xs += xstep;
                    if (xe > GS-1) xe -= xstep;
                    if (xstep == 0) xstep = 1;
                }
                for (int x = xs; x <= xe; x += xstep) {
                    const int cell = cbase + (z * GS + y) * GS + x;
                    const int st  = __ldg(&g_cstart[cell]);
                    const int cnt = __ldg(&g_ccnt[cell]);
                    for (int t = 0; t < cnt; t++) {
                        const float4 s = __ldg(&pts[st + t]);
                        const float dx = qx - s.x, dy = qy - s.y, dz = qz - s.z;
                        const float d2 = __fadd_rn(__fadd_rn(__fmul_rn(dx,dx), __fmul_rn(dy,dy)), __fmul_rn(dz,dz));
                        const int idx = __float_as_int(s.w);
                        const bool lt2 = (d2 < b2) || (d2 == b2 && idx < i2);
                        if (lt2) {
                            const bool lt1 = (d2 < b1) || (d2 == b1 && idx < i1);
                            const bool lt0 = (d2 < b0) || (d2 == b0 && idx < i0);
                            if (lt0)      { b2=b1;i2=i1; b1=b0;i1=i0; b0=d2;i0=idx; }
                            else if (lt1) { b2=b1;i2=i1; b1=d2;i1=idx; }
                            else          { b2=d2;i2=idx; }
                        }
                    }
                }
            }
        }

        // full-coverage termination
        if (xlo == 0 && xhi == GS-1 && ylo == 0 && yhi == GS-1 && zlo == 0 && zhi == GS-1)
            break;
        // pruning bound: any unvisited point lies outside the searched box
        if (b2 < 3.4e38f) {
            const float dmx = fmaxf(0.f, fmaxf((float)(qcx - R) * h - qx, qx - (float)(qcx + R + 1) * h));
            const float dmy = fmaxf(0.f, fmaxf((float)(qcy - R) * h - qy, qy - (float)(qcy + R + 1) * h));
            const float dmz = fmaxf(0.f, fmaxf((float)(qcz - R) * h - qz, qz - (float)(qcz + R + 1) * h));
            const float dmin2 = (dmx*dmx + dmy*dmy + dmz*dmz) * 0.999999f;
            if (dmin2 > b2) break;
        }
    }

    const float w0 = 1.f / (b0 + 1e-8f);
    const float w1 = 1.f / (b1 + 1e-8f);
    const float w2 = 1.f / (b2 + 1e-8f);
    const float inv = 1.f / (w0 + w1 + w2);

    const int fo = gq * 3;
    g_kidx[fo + 0] = bI * n2 + i0;
    g_kidx[fo + 1] = bI * n2 + i1;
    g_kidx[fo + 2] = bI * n2 + i2;
    g_kw[fo + 0] = w0 * inv;
    g_kw[fo + 1] = w1 * inv;
    g_kw[fo + 2] = w2 * inv;
}

// ---------------------------------------------------------------------------
// Inputs (metadata order): p1, x1, o1, p2, x2, o2, w1_feat, w1_dir, w2_feat, w2_dir
// ---------------------------------------------------------------------------
extern "C" void kernel_launch(void* const* d_in, const int* in_sizes, int n_in,
                              void* d_out, int out_size)
{
    const float* p1  = (const float*)d_in[0];
    const float* x1  = (const float*)d_in[1];
    const float* p2  = (const float*)d_in[3];
    const float* x2  = (const float*)d_in[4];
    const float* w1f = (const float*)d_in[6];
    const float* w1d = (const float*)d_in[7];
    const float* w2f = (const float*)d_in[8];
    const float* w2d = (const float*)d_in[9];
    float* out = (float*)d_out;

    const int b    = in_sizes[2];              // 4
    const int N1   = in_sizes[0] / 3;          // 65536
    const int N2   = in_sizes[3] / 3;          // 16384
    const int Cin1 = in_sizes[1] / (3 * N1);   // 64
    const int Cin2 = in_sizes[4] / (3 * N2);   // 128
    const int n1   = N1 / b;
    const int n2   = N2 / b;

    // K1: y2 = VN(x2)  ->  g_y2
    vn_kernel<false><<<(N2 + PTS - 1) / PTS, 256>>>(x2, w2f, w2d, nullptr, Cin2, N2, 0);

    // Grid build + K2: exact k=3 NN  ->  g_kidx / g_kw
    grid_zero<<<(b * NCELLS + 255) / 256, 256>>>(b);
    dim3 cg((n2 + 255) / 256, b);
    grid_count<<<cg, 256>>>(p2, n2);
    grid_scan<<<b, 1024>>>();
    grid_scatter<<<cg, 256>>>(p2, n2);
    dim3 qg((n1 + 255) / 256, b);
    knn_grid_kernel<<<qg, 256>>>(p1, n1, n2);

    // K3: out = VN(x1) + interp(g_y2)
    vn_kernel<true><<<(N1 + PTS - 1) / PTS, 256>>>(x1, w1f, w1d, out, Cin1, N1, N2);
}